// round 10
// baseline (speedup 1.0000x reference)
#include <cuda_runtime.h>
#include <cstdint>

// AggregateLevels: FPN anchor generation + delta decode, 5 levels fused.
// B=16, IH=IW=1024. Levels i=2..6: h=w = 256,128,64,32,16. A = 261888.
// One position per thread-iteration (ALL loads and stores warp-contiguous),
// ILP independent iterations per thread (p0 + k*TPB) for MLP.
// Phase 1 finishes all anchor math and issues all loads; per-k live state is
// 4 anchor floats + 6 load regs. Phase 2 recomputes indices from p0.
// Output (float32): scores [B,A,2] @0 ; boxes [B,A,4] @B*A*2 ; anchors [B,A,4] @B*A*6.

#define B_SZ   16
#define A_TOT  261888
#define TPB    256
#define ILP    4
#define GRIDX  256          // ceil(A_TOT / (TPB*ILP)) = 256

__constant__ int   c_off[5]   = {0, 196608, 245760, 258048, 261120};
__constant__ int   c_lghw[5]  = {16, 14, 12, 10, 8};
__constant__ int   c_lgw[5]   = {8, 7, 6, 5, 4};
__constant__ float c_scale[5] = {4.f, 8.f, 16.f, 32.f, 64.f};
__constant__ float c_half[5]  = {1.5f, 3.5f, 7.5f, 15.5f, 31.5f};
__constant__ float c_anch[5]  = {0.0625f, 0.125f, 0.25f, 0.5f, 1.0f}; // 2^(i-6)

struct Ptrs {
    const float* cs[5];
    const float* bp[5];
    const int*   ih;
    const int*   iw;
};

__global__ __launch_bounds__(TPB, 5)
void aggregate_levels_kernel(Ptrs ptrs, float* __restrict__ out) {
    const int b  = blockIdx.y;
    const int p0 = blockIdx.x * (TPB * ILP) + threadIdx.x;

    const float fih = (float)(*ptrs.ih);
    const float fiw = (float)(*ptrs.iw);

    // ---- phase 1: decode -> anchor floats, issue ALL loads ----
    float acy[ILP], acx[ILP], ah[ILP], aw[ILP];
    float c0[ILP], c1[ILP], d0[ILP], d1[ILP], d2[ILP], d3[ILP];

    #pragma unroll
    for (int k = 0; k < ILP; ++k) {
        const int pk = p0 + k * TPB;
        const int pp = (pk < A_TOT) ? pk : 0;
        const int lv = (pp >= 196608) + (pp >= 245760) + (pp >= 258048) + (pp >= 261120);
        const int q    = pp - c_off[lv];
        const int lghw = c_lghw[lv];
        const int hw   = 1 << lghw;
        const int a    = q >> lghw;           // aspect 0..2
        const int rem  = q & (hw - 1);
        const int lgw  = c_lgw[lv];
        const int y    = rem >> lgw;
        const int x    = rem & ((1 << lgw) - 1);

        const float s  = c_scale[lv];
        const float hc = c_half[lv];
        const float an = c_anch[lv];
        acy[k] = s * (float)y + hc;
        acx[k] = s * (float)x + hc;
        const float ha = fih * an;
        const float wa = fiw * an;
        ah[k] = (a == 2) ? 2.0f * ha : ha;    // hs = {ha, ha, 2ha}
        aw[k] = (a == 0) ? 2.0f * wa : wa;    // ws = {2wa, wa, wa}

        const float* cs = ptrs.cs[lv] + (((b * 6  + a * 2) << lghw) + rem);
        const float* bp = ptrs.bp[lv] + (((b * 12 + a * 4) << lghw) + rem);
        c0[k] = __ldcs(cs);
        c1[k] = __ldcs(cs + hw);
        d0[k] = __ldcs(bp);
        d1[k] = __ldcs(bp + hw);
        d2[k] = __ldcs(bp + 2 * hw);
        d3[k] = __ldcs(bp + 3 * hw);
    }

    // ---- phase 2: decode boxes, store everything ----
    float2* os = reinterpret_cast<float2*>(out);
    float4* ob = reinterpret_cast<float4*>(out + (size_t)B_SZ * A_TOT * 2);
    float4* oa = reinterpret_cast<float4*>(out + (size_t)B_SZ * A_TOT * 6);

    #pragma unroll
    for (int k = 0; k < ILP; ++k) {
        const int pk = p0 + k * TPB;
        if (pk >= A_TOT) continue;

        const float cyc = acy[k] + d0[k] * ah[k];
        const float cxc = acx[k] + d1[k] * aw[k];
        const float hh  = ah[k] * __expf(d2[k]);
        const float ww  = aw[k] * __expf(d3[k]);

        const float y1 = fminf(fmaxf(cyc - 0.5f * hh, 0.0f), fih);
        const float x1 = fminf(fmaxf(cxc - 0.5f * ww, 0.0f), fiw);
        const float y2 = fminf(fmaxf(cyc + 0.5f * hh, 0.0f), fih);
        const float x2 = fminf(fmaxf(cxc + 0.5f * ww, 0.0f), fiw);

        const size_t idx = (size_t)b * A_TOT + pk;
        __stcs(os + idx, make_float2(c0[k], c1[k]));
        __stcs(ob + idx, make_float4(y1, x1, y2, x2));
        __stcs(oa + idx, make_float4(acy[k], acx[k], ah[k], aw[k]));
    }
}

extern "C" void kernel_launch(void* const* d_in, const int* in_sizes, int n_in,
                              void* d_out, int out_size) {
    (void)out_size;
    // Identify inputs by element count (robust to metadata ordering).
    // Level l=0..4 (FPN i=l+2): hw = 65536>>(2*l); cs has 16*6*hw elems,
    // bp has 16*12*hw elems; all counts distinct. Scalars have size 1
    // (dict order: img_h then img_w).
    Ptrs ptrs;
    ptrs.ih = nullptr; ptrs.iw = nullptr;
    for (int i = 0; i < n_in; ++i) {
        const long long sz = in_sizes[i];
        if (sz == 1) {
            if (!ptrs.ih) ptrs.ih = (const int*)d_in[i];
            else          ptrs.iw = (const int*)d_in[i];
            continue;
        }
        for (int l = 0; l < 5; ++l) {
            const long long hw = 65536LL >> (2 * l);
            if (sz == 16LL * 6 * hw)  ptrs.cs[l] = (const float*)d_in[i];
            if (sz == 16LL * 12 * hw) ptrs.bp[l] = (const float*)d_in[i];
        }
    }

    dim3 grid(GRIDX, B_SZ);
    aggregate_levels_kernel<<<grid, TPB>>>(ptrs, (float*)d_out);
}